// round 13
// baseline (speedup 1.0000x reference)
#include <cuda_runtime.h>
#include <cuda_fp16.h>

#define HH    256
#define WW    256
#define C_IN  128
#define C_OUT 256
#define KTOT  1152

// ---------------- device scratch (static, no allocation) ----------------
__device__ __half g_Xh[(size_t)HH * WW * C_IN];   // [y][x][ci] fp16
__device__ __half g_Wh[C_OUT * KTOT];             // [co][kh][cic][kw][ci32] fp16

// ---------------- helpers ----------------
__device__ __forceinline__ void cpasync16(void* dst_smem, const void* src_gmem) {
    unsigned d = (unsigned)__cvta_generic_to_shared(dst_smem);
    asm volatile("cp.async.cg.shared.global [%0], [%1], 16;"
                 :: "r"(d), "l"(__cvta_generic_to_global(src_gmem)) : "memory");
}
__device__ __forceinline__ void sts_zero16(void* dst_smem) {
    unsigned d = (unsigned)__cvta_generic_to_shared(dst_smem);
    asm volatile("st.shared.v4.b32 [%0], {%1,%1,%1,%1};" :: "r"(d), "r"(0) : "memory");
}
#define CP_COMMIT() asm volatile("cp.async.commit_group;" ::: "memory")
#define CP_WAIT(N)  asm volatile("cp.async.wait_group %0;" :: "n"(N) : "memory")

__device__ __forceinline__ void mma16816(float* d, const unsigned* a, const unsigned* b) {
    asm volatile("mma.sync.aligned.m16n8k16.row.col.f32.f16.f16.f32 "
                 "{%0,%1,%2,%3}, {%4,%5,%6,%7}, {%8,%9}, {%0,%1,%2,%3};"
                 : "+f"(d[0]), "+f"(d[1]), "+f"(d[2]), "+f"(d[3])
                 : "r"(a[0]), "r"(a[1]), "r"(a[2]), "r"(a[3]), "r"(b[0]), "r"(b[1]));
}
__device__ __forceinline__ void ldmat4(unsigned* r, unsigned addr) {
    asm volatile("ldmatrix.sync.aligned.m8n8.x4.shared.b16 {%0,%1,%2,%3}, [%4];"
                 : "=r"(r[0]), "=r"(r[1]), "=r"(r[2]), "=r"(r[3]) : "r"(addr));
}

// ================= fused prep =================
// blocks [0, 2048): X transpose+convert, 32-px tile.  blocks [2048, 2304): W reorder.
#define XP_STRIDE 130
__global__ __launch_bounds__(128) void prep_kernel(const float* __restrict__ x,
                                                   const float* __restrict__ w) {
    const int bid = blockIdx.x;
    const int tid = threadIdx.x;

    if (bid >= 2048) {
        // ---- W reorder: dest k' = kh(3) x cic(4) x kw(3) x ci32(32); src w[co][ci][kh][kw]
        const int co = bid - 2048;
        for (int k = tid; k < KTOT; k += 128) {
            int kh = k / 384, r0 = k % 384;
            int cic = r0 / 96, r1 = r0 % 96;
            int kw = r1 / 32, ci5 = r1 % 32;
            int ci = cic * 32 + ci5;
            g_Wh[co * KTOT + k] = __float2half_rn(w[co * KTOT + ci * 9 + kh * 3 + kw]);
        }
        return;
    }

    // ---- X: [ci][y][x] f32 -> [y][x][ci] fp16, 32-px tile ----
    __shared__ __half sh[32 * XP_STRIDE];   // [x 32][ci 128]
    const int xt = bid & 7;                 // 32-px eighth of the row
    const int y  = bid >> 3;
    const int xbase = xt * 32;
    const int pp = (tid & 15) * 2;          // pixel pair
    const int cp = tid >> 4;                // ci-pair group 0..7

    #pragma unroll
    for (int it = 0; it < 8; it++) {
        const int ci0 = (cp + it * 8) * 2;
        const float* r0 = x + ((size_t)ci0 * HH + y) * WW + xbase;
        const float* r1 = r0 + (size_t)HH * WW;
        float2 a = *(const float2*)(r0 + pp);
        float2 b = *(const float2*)(r1 + pp);
        *(__half2*)&sh[(pp    ) * XP_STRIDE + ci0] = __floats2half2_rn(a.x, b.x);
        *(__half2*)&sh[(pp + 1) * XP_STRIDE + ci0] = __floats2half2_rn(a.y, b.y);
    }
    __syncthreads();

    #pragma unroll
    for (int p = 0; p < 4; p++) {
        int idx = p * 128 + tid;
        int row = idx >> 4, c = idx & 15;
        const unsigned* s = (const unsigned*)&sh[row * XP_STRIDE + c * 8];
        uint4 v = make_uint4(s[0], s[1], s[2], s[3]);
        *(uint4*)&g_Xh[((size_t)(y * WW + xbase + row)) * C_IN + c * 8] = v;
    }
}

// ================= main: 128co x 64px CTA (128 thr), 2-stage, 3 CTA/SM =================
#define XT_STRIDE 40    // halves (80B; ldmatrix rows bank-disjoint)
#define WS_STRIDE 104   // halves (208B; ldmatrix rows bank-disjoint)
#define XCOLS  66       // gx = x0-1 .. x0+64
#define OFF_X  0
#define OFF_WH (XCOLS * XT_STRIDE * 2)          // 5280
#define STAGE  (OFF_WH + 128 * WS_STRIDE * 2)   // 31904
#define SM_TOTAL (2 * STAGE)                    // 63808

__global__ __launch_bounds__(128, 3) void conv_mma_kernel(
    const float* __restrict__ bias, float* __restrict__ out)
{
    extern __shared__ char sm[];

    const int tid = threadIdx.x, wid = tid >> 5, lane = tid & 31;
    const int g = lane >> 2, r = lane & 3;
    const int x0  = blockIdx.x * 64;
    const int y   = blockIdx.y;
    const int coH = blockIdx.z;
    const int warp_co = wid * 32;    // 4 warps cover 128 co; all share the 64-px range

    float d[2][8][4];
    #pragma unroll
    for (int mt = 0; mt < 2; mt++)
        #pragma unroll
        for (int nt = 0; nt < 8; nt++)
            #pragma unroll
            for (int q = 0; q < 4; q++) d[mt][nt][q] = 0.0f;

    // per-thread ldmatrix base offsets (halves; <<1 for bytes)
    const unsigned aRow = (unsigned)((warp_co + (lane & 15)) * WS_STRIDE + ((lane >> 4) << 3));
    const unsigned bRow = (unsigned)((lane & 7) * XT_STRIDE + ((lane >> 3) << 3));

    // ---- chunk loader: chunk c = (kh, cic) ----
    auto load_chunk = [&](int c, char* st) {
        const int kh = c >> 2, cic = c & 3;
        const int yy = y + kh - 1;
        const bool yv = (unsigned)yy < (unsigned)HH;
        __half* xs = (__half*)(st + OFF_X);
        __half* wh = (__half*)(st + OFF_WH);

        // X: 66 cols x 4 gi = 264 cp.async
        #pragma unroll
        for (int i0 = 0; i0 < 3; i0++) {
            int i = tid + i0 * 128;
            if (i < XCOLS * 4) {
                int col = i >> 2, gi = i & 3;
                int gx = x0 + col - 1;
                __half* dst = xs + col * XT_STRIDE + gi * 8;
                if (yv && (unsigned)gx < (unsigned)WW)
                    cpasync16(dst, g_Xh + ((size_t)(yy * WW + gx) * C_IN + cic * 32 + gi * 8));
                else
                    sts_zero16(dst);
            }
        }
        // W: 128 co x 12 gi = 1536 cp.async
        #pragma unroll
        for (int i0 = 0; i0 < 12; i0++) {
            int i = tid + i0 * 128;
            int co = i / 12, gi = i % 12;
            size_t o = (size_t)(coH * 128 + co) * KTOT + (kh * 4 + cic) * 96 + gi * 8;
            cpasync16(wh + co * WS_STRIDE + gi * 8, g_Wh + o);
        }
        CP_COMMIT();
    };

    load_chunk(0, sm);

    for (int c = 0; c < 12; c++) {
        char* cur = sm + (c & 1) * STAGE;
        if (c < 11) {
            load_chunk(c + 1, sm + ((c + 1) & 1) * STAGE);
            CP_WAIT(1);
        } else {
            CP_WAIT(0);
        }
        __syncthreads();

        const unsigned xs_s = (unsigned)__cvta_generic_to_shared(cur + OFF_X) + (bRow << 1);
        const unsigned wh_s = (unsigned)__cvta_generic_to_shared(cur + OFF_WH) + (aRow << 1);

        #pragma unroll
        for (int kw = 0; kw < 3; kw++) {
            unsigned a[2][2][4];   // [ks][mt][4]
            #pragma unroll
            for (int ks = 0; ks < 2; ks++)
                #pragma unroll
                for (int mt = 0; mt < 2; mt++)
                    ldmat4(a[ks][mt], wh_s + ((unsigned)(mt * 16 * WS_STRIDE + kw * 32 + ks * 16) << 1));
            #pragma unroll
            for (int nt = 0; nt < 8; nt++) {
                unsigned b[4];   // k0..31 of this chunk; kw shifts ONLY the pixel column
                ldmat4(b, xs_s + ((unsigned)((nt * 8 + kw) * XT_STRIDE) << 1));
                mma16816(d[0][nt], a[0][0], b);
                mma16816(d[1][nt], a[0][1], b);
                mma16816(d[0][nt], a[1][0], b + 2);
                mma16816(d[1][nt], a[1][1], b + 2);
            }
        }
        __syncthreads();   // all warps done with `cur` before refill
    }

    // ---- epilogue: bias + float2 stores ----
    #pragma unroll
    for (int mt = 0; mt < 2; mt++) {
        int co0 = coH * 128 + warp_co + mt * 16 + g;
        int co1 = co0 + 8;
        float b0 = bias[co0], b1 = bias[co1];
        float* row0 = out + (size_t)co0 * (HH * WW) + y * WW + x0;
        float* row1 = out + (size_t)co1 * (HH * WW) + y * WW + x0;
        #pragma unroll
        for (int nt = 0; nt < 8; nt++) {
            int px = nt * 8 + 2 * r;
            *(float2*)(row0 + px) = make_float2(d[mt][nt][0] + b0, d[mt][nt][1] + b0);
            *(float2*)(row1 + px) = make_float2(d[mt][nt][2] + b1, d[mt][nt][3] + b1);
        }
    }
}

// ================= launcher =================
extern "C" void kernel_launch(void* const* d_in, const int* in_sizes, int n_in,
                              void* d_out, int out_size) {
    const float* x    = (const float*)d_in[0];
    const float* w    = (const float*)d_in[1];
    const float* bias = (const float*)d_in[2];
    float* out        = (float*)d_out;

    cudaFuncSetAttribute(conv_mma_kernel, cudaFuncAttributeMaxDynamicSharedMemorySize, SM_TOTAL);

    prep_kernel<<<2304, 128>>>(x, w);
    conv_mma_kernel<<<dim3(4, HH, 2), 128, SM_TOTAL>>>(bias, out);
}

// round 14
// speedup vs baseline: 1.1145x; 1.1145x over previous
#include <cuda_runtime.h>
#include <cuda_fp16.h>

#define HH    256
#define WW    256
#define C_IN  128
#define C_OUT 256
#define KTOT  1152

// ---------------- device scratch (static, no allocation) ----------------
__device__ __half g_Xh[(size_t)HH * WW * C_IN];   // [y][x][ci] fp16
__device__ __half g_Wh[C_OUT * KTOT];             // [co][kh][cic][kw][ci32] fp16

// ---------------- helpers ----------------
__device__ __forceinline__ void cpasync16(void* dst_smem, const void* src_gmem) {
    unsigned d = (unsigned)__cvta_generic_to_shared(dst_smem);
    asm volatile("cp.async.cg.shared.global [%0], [%1], 16;"
                 :: "r"(d), "l"(__cvta_generic_to_global(src_gmem)) : "memory");
}
__device__ __forceinline__ void sts_zero16(void* dst_smem) {
    unsigned d = (unsigned)__cvta_generic_to_shared(dst_smem);
    asm volatile("st.shared.v4.b32 [%0], {%1,%1,%1,%1};" :: "r"(d), "r"(0) : "memory");
}
#define CP_COMMIT() asm volatile("cp.async.commit_group;" ::: "memory")
#define CP_WAIT(N)  asm volatile("cp.async.wait_group %0;" :: "n"(N) : "memory")

__device__ __forceinline__ void mma16816(float* d, const unsigned* a, const unsigned* b) {
    asm volatile("mma.sync.aligned.m16n8k16.row.col.f32.f16.f16.f32 "
                 "{%0,%1,%2,%3}, {%4,%5,%6,%7}, {%8,%9}, {%0,%1,%2,%3};"
                 : "+f"(d[0]), "+f"(d[1]), "+f"(d[2]), "+f"(d[3])
                 : "r"(a[0]), "r"(a[1]), "r"(a[2]), "r"(a[3]), "r"(b[0]), "r"(b[1]));
}
__device__ __forceinline__ void ldmat4(unsigned* r, unsigned addr) {
    asm volatile("ldmatrix.sync.aligned.m8n8.x4.shared.b16 {%0,%1,%2,%3}, [%4];"
                 : "=r"(r[0]), "=r"(r[1]), "=r"(r[2]), "=r"(r[3]) : "r"(addr));
}

// ================= fused prep: X transpose+convert AND W reorder+convert =================
#define XP_STRIDE 130
__global__ __launch_bounds__(256) void prep_kernel(const float* __restrict__ x,
                                                   const float* __restrict__ w) {
    const int bid = blockIdx.x;
    const int tid = threadIdx.x;

    if (bid >= 1024) {
        // ---- W reorder: dest k' = kh(3) x cic(4) x kw(3) x ci32(32); src w[co][ci][kh][kw]
        const int co = bid - 1024;
        for (int k = tid; k < KTOT; k += 256) {
            int kh = k / 384, r0 = k % 384;
            int cic = r0 / 96, r1 = r0 % 96;
            int kw = r1 / 32, ci5 = r1 % 32;
            int ci = cic * 32 + ci5;
            g_Wh[co * KTOT + k] = __float2half_rn(w[co * KTOT + ci * 9 + kh * 3 + kw]);
        }
        return;
    }

    // ---- X: [ci][y][x] f32 -> [y][x][ci] fp16, 64-px tile ----
    __shared__ __half sh[64 * XP_STRIDE];
    const int xq = bid & 3;
    const int y  = bid >> 2;
    const int wid = tid >> 5, lane = tid & 31;
    const int xbase = xq * 64;

    #pragma unroll
    for (int it = 0; it < 8; it++) {
        const int ci0 = (wid * 8 + it) * 2;
        const float* r0 = x + ((size_t)ci0 * HH + y) * WW + xbase;
        const float* r1 = r0 + (size_t)HH * WW;
        int px = 2 * lane;
        float2 a = *(const float2*)(r0 + px);
        float2 b = *(const float2*)(r1 + px);
        *(__half2*)&sh[(px    ) * XP_STRIDE + ci0] = __floats2half2_rn(a.x, b.x);
        *(__half2*)&sh[(px + 1) * XP_STRIDE + ci0] = __floats2half2_rn(a.y, b.y);
    }
    __syncthreads();

    #pragma unroll
    for (int p = 0; p < 4; p++) {
        int idx = p * 256 + tid;
        int row = idx >> 4, c = idx & 15;
        const unsigned* s = (const unsigned*)&sh[row * XP_STRIDE + c * 8];
        uint4 v = make_uint4(s[0], s[1], s[2], s[3]);
        *(uint4*)&g_Xh[((size_t)(y * WW + xbase + row)) * C_IN + c * 8] = v;
    }
}

// ================= main: 128co x 128px, 3-stage pipeline, bias-init accumulators =================
#define XT_STRIDE 40    // halves (80B; ldmatrix rows bank-disjoint)
#define WS_STRIDE 104   // halves (208B; ldmatrix rows bank-disjoint)
#define OFF_X  0
#define OFF_WH 10400
#define STAGE  37024
#define SM_TOTAL (3 * STAGE)   // 111072

__global__ __launch_bounds__(256, 2) void conv_mma_kernel(
    const float* __restrict__ bias, float* __restrict__ out)
{
    extern __shared__ char sm[];

    const int tid = threadIdx.x, wid = tid >> 5, lane = tid & 31;
    const int g = lane >> 2, r = lane & 3;
    const int x0  = blockIdx.x * 128;
    const int y   = blockIdx.y;
    const int coH = blockIdx.z;
    const int warp_co = (wid & 3) * 32;
    const int warp_px = (wid >> 2) * 64;

    // accumulators pre-loaded with bias: rows co0 (d[0..1]) and co0+8 (d[2..3])
    float d[2][8][4];
    #pragma unroll
    for (int mt = 0; mt < 2; mt++) {
        const int co0 = coH * 128 + warp_co + mt * 16 + g;
        const float b0 = bias[co0];
        const float b1 = bias[co0 + 8];
        #pragma unroll
        for (int nt = 0; nt < 8; nt++) {
            d[mt][nt][0] = b0; d[mt][nt][1] = b0;
            d[mt][nt][2] = b1; d[mt][nt][3] = b1;
        }
    }

    // per-thread ldmatrix base offsets (halves; <<1 for bytes)
    const unsigned aRow = (unsigned)((warp_co + (lane & 15)) * WS_STRIDE + ((lane >> 4) << 3));
    const unsigned bRow = (unsigned)((warp_px + (lane & 7)) * XT_STRIDE + ((lane >> 3) << 3));

    // ---- chunk loader: chunk c = (kh, cic) ----
    auto load_chunk = [&](int c, char* st) {
        const int kh = c >> 2, cic = c & 3;
        const int yy = y + kh - 1;
        const bool yv = (unsigned)yy < (unsigned)HH;
        __half* xs = (__half*)(st + OFF_X);
        __half* wh = (__half*)(st + OFF_WH);

        #pragma unroll
        for (int i0 = 0; i0 < 3; i0++) {
            int i = tid + i0 * 256;
            if (i < 520) {
                int col = i >> 2, gi = i & 3;
                int gx = x0 + col - 1;
                __half* dst = xs + col * XT_STRIDE + gi * 8;
                if (yv && (unsigned)gx < (unsigned)WW)
                    cpasync16(dst, g_Xh + ((size_t)(yy * WW + gx) * C_IN + cic * 32 + gi * 8));
                else
                    sts_zero16(dst);
            }
        }
        #pragma unroll
        for (int i0 = 0; i0 < 6; i0++) {
            int i = tid + i0 * 256;
            int co = i / 12, gi = i % 12;
            size_t o = (size_t)(coH * 128 + co) * KTOT + (kh * 4 + cic) * 96 + gi * 8;
            cpasync16(wh + co * WS_STRIDE + gi * 8, g_Wh + o);
        }
    };

    load_chunk(0, sm);             CP_COMMIT();
    load_chunk(1, sm + STAGE);     CP_COMMIT();

    for (int c = 0; c < 12; c++) {
        CP_WAIT(1);          // chunk c landed
        __syncthreads();     // visible to all; buf (c-1)%3 free

        if (c < 10) load_chunk(c + 2, sm + ((c + 2) % 3) * STAGE);
        CP_COMMIT();         // uniform accounting

        char* cur = sm + (c % 3) * STAGE;
        const unsigned xs_s = (unsigned)__cvta_generic_to_shared(cur + OFF_X) + (bRow << 1);
        const unsigned wh_s = (unsigned)__cvta_generic_to_shared(cur + OFF_WH) + (aRow << 1);

        // B-fragment double buffer: prefetch (kw,nt)+1 before the HMMAs of (kw,nt).
        unsigned b0[4], b1[4];
        ldmat4(b0, xs_s);   // (kw=0, nt=0): col warp_px+0

        #pragma unroll
        for (int kw = 0; kw < 3; kw++) {
            unsigned a[2][2][4];   // [ks][mt][4]
            #pragma unroll
            for (int ks = 0; ks < 2; ks++)
                #pragma unroll
                for (int mt = 0; mt < 2; mt++)
                    ldmat4(a[ks][mt], wh_s + ((unsigned)(mt * 16 * WS_STRIDE + kw * 32 + ks * 16) << 1));
            #pragma unroll
            for (int nt = 0; nt < 8; nt++) {
                const int idx = kw * 8 + nt;
                unsigned* bc = (idx & 1) ? b1 : b0;
                unsigned* bn = (idx & 1) ? b0 : b1;
                if (idx < 23) {
                    const int ni  = idx + 1;
                    const int nkw = ni >> 3, nnt = ni & 7;
                    ldmat4(bn, xs_s + ((unsigned)((nnt * 8 + nkw) * XT_STRIDE) << 1));
                }
                mma16816(d[0][nt], a[0][0], bc);
                mma16816(d[1][nt], a[0][1], bc);
                mma16816(d[0][nt], a[1][0], bc + 2);
                mma16816(d[1][nt], a[1][1], bc + 2);
            }
        }
    }

    // ---- epilogue: bias already in accumulators; straight float2 stores ----
    #pragma unroll
    for (int mt = 0; mt < 2; mt++) {
        int co0 = coH * 128 + warp_co + mt * 16 + g;
        int co1 = co0 + 8;
        float* row0 = out + (size_t)co0 * (HH * WW) + y * WW + x0;
        float* row1 = out + (size_t)co1 * (HH * WW) + y * WW + x0;
        #pragma unroll
        for (int nt = 0; nt < 8; nt++) {
            int px = warp_px + nt * 8 + 2 * r;
            *(float2*)(row0 + px) = make_float2(d[mt][nt][0], d[mt][nt][1]);
            *(float2*)(row1 + px) = make_float2(d[mt][nt][2], d[mt][nt][3]);
        }
    }
}

// ================= launcher =================
extern "C" void kernel_launch(void* const* d_in, const int* in_sizes, int n_in,
                              void* d_out, int out_size) {
    const float* x    = (const float*)d_in[0];
    const float* w    = (const float*)d_in[1];
    const float* bias = (const float*)d_in[2];
    float* out        = (float*)d_out;

    cudaFuncSetAttribute(conv_mma_kernel, cudaFuncAttributeMaxDynamicSharedMemorySize, SM_TOTAL);

    prep_kernel<<<1280, 256>>>(x, w);
    conv_mma_kernel<<<dim3(2, HH, 2), 256, SM_TOTAL>>>(bias, out);
}